// round 8
// baseline (speedup 1.0000x reference)
#include <cuda_runtime.h>
#include <cstdint>

#define T_STEPS 512
#define BATCH   2048
#define F_IN    64
#define HID     32
#define NGATE   128   // 4*HID
#define PFD     3     // prefetch distance (steps)

typedef unsigned long long ull;

// x_proj scratch, CELL-MAJOR gate quads: entry [t][b][cell*4 + gtype].
// Padded by 4 steps so distance-PFD prefetch never reads out of bounds.
__device__ float g_xproj[(size_t)(T_STEPS + 4) * BATCH * NGATE];

__device__ __forceinline__ ull pack2(float lo, float hi) {
    ull r;
    asm("mov.b64 %0, {%1,%2};" : "=l"(r) : "f"(lo), "f"(hi));
    return r;
}
__device__ __forceinline__ void unpack2(ull p, float &lo, float &hi) {
    asm("mov.b64 {%0,%1}, %2;" : "=f"(lo), "=f"(hi) : "l"(p));
}
// packed f32x2 fma: d = a*b + c (lane-wise)
__device__ __forceinline__ ull fma2(ull a, ull b, ull c) {
    ull d;
    asm("fma.rn.f32x2 %0, %1, %2, %3;" : "=l"(d) : "l"(a), "l"(b), "l"(c));
    return d;
}

__device__ __forceinline__ float tanh_fast(float x) {
    float y;
    asm("tanh.approx.f32 %0, %1;" : "=f"(y) : "f"(x));
    return y;
}
__device__ __forceinline__ float sigm_fast(float x) {
    return fmaf(0.5f, tanh_fast(0.5f * x), 0.5f);
}

// ============================================================================
// Kernel A: x_proj = x @ W_ih^T + (b_ih + b_hh)   -- [1M, 64] x [64, 128]
// 128-thread CTA, 64-sample tile; thread tile 8 samples x 8 gates.
// Per 2-kk: 16 LDS.128 feed 128 FFMA2 (2.0 B/FFMA2 -> at/below crossbar).
// ============================================================================
#define XS   64     // samples per CTA
#define WPIT 34     // ull pitch (32 data + 2 pad)

__global__ void __launch_bounds__(128)
xproj_kernel(const float* __restrict__ x,
             const float* __restrict__ W_ih,
             const float* __restrict__ b_ih,
             const float* __restrict__ b_hh)
{
    __shared__ __align__(16) ull wrow[NGATE * WPIT];  // 34816 B
    __shared__ __align__(16) ull xrow[XS * WPIT];     // 17408 B

    const int t  = threadIdx.x;
    const int tx = t & 15;               // gates: tx + 16p, p=0..7
    const int ty = t >> 4;               // samples: ty*8 .. ty*8+7
    const size_t row0 = (size_t)blockIdx.x * XS;

    // ---- stage W (32 KB) coalesced: 16 float4/thread ----
    {
        const float4* wg = reinterpret_cast<const float4*>(W_ih);
#pragma unroll
        for (int i = 0; i < 16; i++) {
            const int idx = t + 128 * i;      // float4 index, g-major
            const int g = idx >> 4;
            const int c = idx & 15;
            const float4 v = wg[idx];
            *reinterpret_cast<ulonglong2*>(&wrow[g * WPIT + 2 * c]) =
                make_ulonglong2(pack2(v.x, v.y), pack2(v.z, v.w));
        }
    }
    // ---- stage x tile (16 KB) coalesced: 8 float4/thread ----
    {
        const float4* xg = reinterpret_cast<const float4*>(x + row0 * F_IN);
#pragma unroll
        for (int i = 0; i < 8; i++) {
            const int idx = t + 128 * i;
            const int s = idx >> 4;
            const int c = idx & 15;
            const float4 v = xg[idx];
            *reinterpret_cast<ulonglong2*>(&xrow[s * WPIT + 2 * c]) =
                make_ulonglong2(pack2(v.x, v.y), pack2(v.z, v.w));
        }
    }

    // ---- acc init with bias in lo lane ----
    ull acc[8][8];
    {
#pragma unroll
        for (int p = 0; p < 8; p++) {
            const int g = tx + 16 * p;
            const ull b = pack2(b_ih[g] + b_hh[g], 0.0f);
#pragma unroll
            for (int q = 0; q < 8; q++) acc[q][p] = b;
        }
    }
    __syncthreads();

    // ---- main loop: per 2 kk: 16 LDS.128 feed 128 FFMA2 ----
#pragma unroll 2
    for (int kk = 0; kk < 32; kk += 2) {
        ulonglong2 xq[8], wq[8];
#pragma unroll
        for (int q = 0; q < 8; q++)
            xq[q] = *reinterpret_cast<const ulonglong2*>(
                &xrow[(ty * 8 + q) * WPIT + kk]);
#pragma unroll
        for (int p = 0; p < 8; p++)
            wq[p] = *reinterpret_cast<const ulonglong2*>(
                &wrow[(tx + 16 * p) * WPIT + kk]);
#pragma unroll
        for (int q = 0; q < 8; q++)
#pragma unroll
            for (int p = 0; p < 8; p++) {
                acc[q][p] = fma2(xq[q].x, wq[p].x, acc[q][p]);
                acc[q][p] = fma2(xq[q].y, wq[p].y, acc[q][p]);
            }
    }

    // ---- writeout: cell-major gate quads, coalesced STG.128 ----
#pragma unroll
    for (int q = 0; q < 8; q++) {
        float hlo, hhi;
        float4 v0, v1;
        unpack2(acc[q][0], hlo, hhi); v0.x = hlo + hhi;   // type 0, cell tx
        unpack2(acc[q][2], hlo, hhi); v0.y = hlo + hhi;   // type 1
        unpack2(acc[q][4], hlo, hhi); v0.z = hlo + hhi;   // type 2
        unpack2(acc[q][6], hlo, hhi); v0.w = hlo + hhi;   // type 3
        unpack2(acc[q][1], hlo, hhi); v1.x = hlo + hhi;   // cell tx+16
        unpack2(acc[q][3], hlo, hhi); v1.y = hlo + hhi;
        unpack2(acc[q][5], hlo, hhi); v1.z = hlo + hhi;
        unpack2(acc[q][7], hlo, hhi); v1.w = hlo + hhi;
        float4* op4 = reinterpret_cast<float4*>(
            g_xproj + (row0 + ty * 8 + q) * NGATE);
        op4[tx]      = v0;
        op4[tx + 16] = v1;
    }
}

// ============================================================================
// Kernel B: recurrence, single-warp CTA, ONE sample per warp (2048 warps ->
// ~14 warps/SM for latency hiding). Lane t owns cell t. True register ring
// (fully-unrolled x4) keeps the x_proj LDG ~3 steps in flight.
// ============================================================================
__global__ void __launch_bounds__(32)
recur_kernel(const float* __restrict__ W_hh,
             const float* __restrict__ W_d,
             const float* __restrict__ b_d,
             float* __restrict__ out)
{
    __shared__ ull hp[2][HID / 2];     // double-buffered h pairs, 256 B

    const int t = threadIdx.x;         // lane = cell index
    const int b = blockIdx.x;          // sample

    // weight rows t, t+32, t+64, t+96 packed along k
    ull wI[16], wF[16], wG[16], wO[16];
    {
        const ull* wr = reinterpret_cast<const ull*>(W_hh);
#pragma unroll
        for (int kk = 0; kk < 16; kk++) {
            wI[kk] = wr[(t)      * 16 + kk];
            wF[kk] = wr[(t + 32) * 16 + kk];
            wG[kk] = wr[(t + 64) * 16 + kk];
            wO[kk] = wr[(t + 96) * 16 + kk];
        }
    }

    if (t < HID / 2) hp[0][t] = 0ULL;
    float c = 0.0f;

    const float4* xq = reinterpret_cast<const float4*>(
        g_xproj + (size_t)b * NGATE) + t;
    const size_t s4 = (size_t)BATCH * NGATE / 4;   // float4 step stride

    // prefetch ring: buf[i&3] holds step i's quad
    float4 buf[4];
    buf[0] = xq[0];
    buf[1] = xq[s4];
    buf[2] = xq[2 * s4];
    __syncwarp();

#pragma unroll 1
    for (int ts0 = 0; ts0 < T_STEPS; ts0 += 4) {
#pragma unroll
        for (int u = 0; u < 4; u++) {
            const int ts = ts0 + u;
            // issue load for ts+PFD into the slot freed last step
            buf[(ts + PFD) & 3] = xq[(size_t)(ts + PFD) * s4];

            const float4 cur = buf[ts & 3];
            const int rb = ts & 1;
            const ulonglong2* hq = reinterpret_cast<const ulonglong2*>(hp[rb]);

            // phase 1: 4 gate rows, h broadcast from smem
            ull aI = pack2(cur.x, 0.0f);
            ull aF = pack2(cur.y, 0.0f);
            ull aG = pack2(cur.z, 0.0f);
            ull aO = pack2(cur.w, 0.0f);
#pragma unroll
            for (int k2 = 0; k2 < 8; k2++) {
                const ulonglong2 hv = hq[k2];
                aI = fma2(hv.x, wI[2 * k2], aI);
                aF = fma2(hv.x, wF[2 * k2], aF);
                aG = fma2(hv.x, wG[2 * k2], aG);
                aO = fma2(hv.x, wO[2 * k2], aO);
                aI = fma2(hv.y, wI[2 * k2 + 1], aI);
                aF = fma2(hv.y, wF[2 * k2 + 1], aF);
                aG = fma2(hv.y, wG[2 * k2 + 1], aG);
                aO = fma2(hv.y, wO[2 * k2 + 1], aO);
            }
            float lo, hi;
            unpack2(aI, lo, hi); const float ig = sigm_fast(lo + hi);
            unpack2(aF, lo, hi); const float fg = sigm_fast(lo + hi);
            unpack2(aG, lo, hi); const float gg = tanh_fast(lo + hi);
            unpack2(aO, lo, hi); const float og = sigm_fast(lo + hi);

            // phase 2: thread-local cell update, write to OTHER buffer
            c = fg * c + ig * gg;
            const float h = og * tanh_fast(c);
            reinterpret_cast<float*>(hp[1 - rb])[t] = h;

            __syncwarp();   // h buffer (1-rb) visible for next step
        }
    }

    // epilogue: out[b, a] = relu(h_T) @ W_d^T + b_d
    // final h in buffer 1-((T-1)&1) = T&1 = 0
    if (t < 3) {
        float sum = b_d[t];
        const float* hf = reinterpret_cast<const float*>(hp[T_STEPS & 1]);
#pragma unroll
        for (int j = 0; j < HID; j++)
            sum += fmaxf(hf[j], 0.0f) * W_d[t * HID + j];
        out[(size_t)b * 3 + t] = sum;
    }
}

extern "C" void kernel_launch(void* const* d_in, const int* in_sizes, int n_in,
                              void* d_out, int out_size)
{
    const float* x    = (const float*)d_in[0];
    const float* W_ih = (const float*)d_in[1];
    const float* W_hh = (const float*)d_in[2];
    const float* b_ih = (const float*)d_in[3];
    const float* b_hh = (const float*)d_in[4];
    const float* W_d  = (const float*)d_in[5];
    const float* b_d  = (const float*)d_in[6];
    float* out = (float*)d_out;

    // Kernel A: x_proj GEMM over all timesteps (no recurrence)
    {
        dim3 grid((T_STEPS * BATCH) / XS);   // 16384 CTAs
        dim3 block(128);
        xproj_kernel<<<grid, block>>>(x, W_ih, b_ih, b_hh);
    }
    // Kernel B: sequential LSTM recurrence + decode head
    {
        dim3 grid(BATCH);                    // 2048 single-warp CTAs
        dim3 block(32);
        recur_kernel<<<grid, block>>>(W_hh, W_d, b_d, out);
    }
}

// round 9
// speedup vs baseline: 1.0938x; 1.0938x over previous
#include <cuda_runtime.h>
#include <cstdint>

#define T_STEPS 512
#define BATCH   2048
#define F_IN    64
#define HID     32
#define NGATE   128   // 4*HID
#define PFD     3     // prefetch distance (steps)

typedef unsigned long long ull;

// x_proj scratch, CELL-MAJOR gate quads: entry [t][b][cell*4 + gtype].
// Padded by 4 steps so distance-PFD prefetch never reads out of bounds.
__device__ float g_xproj[(size_t)(T_STEPS + 4) * BATCH * NGATE];

__device__ __forceinline__ ull pack2(float lo, float hi) {
    ull r;
    asm("mov.b64 %0, {%1,%2};" : "=l"(r) : "f"(lo), "f"(hi));
    return r;
}
__device__ __forceinline__ void unpack2(ull p, float &lo, float &hi) {
    asm("mov.b64 {%0,%1}, %2;" : "=f"(lo), "=f"(hi) : "l"(p));
}
// packed f32x2 fma: d = a*b + c (lane-wise)
__device__ __forceinline__ ull fma2(ull a, ull b, ull c) {
    ull d;
    asm("fma.rn.f32x2 %0, %1, %2, %3;" : "=l"(d) : "l"(a), "l"(b), "l"(c));
    return d;
}

__device__ __forceinline__ float tanh_fast(float x) {
    float y;
    asm("tanh.approx.f32 %0, %1;" : "=f"(y) : "f"(x));
    return y;
}
__device__ __forceinline__ float sigm_fast(float x) {
    return fmaf(0.5f, tanh_fast(0.5f * x), 0.5f);
}

// 16-byte async copy gmem -> smem (L1-bypass); completion via commit/wait groups
__device__ __forceinline__ void cp16(void* smem, const void* gmem) {
    uint32_t s = (uint32_t)__cvta_generic_to_shared(smem);
    asm volatile("cp.async.cg.shared.global [%0], [%1], 16;" :: "r"(s), "l"(gmem));
}

// ============================================================================
// Kernel A: x_proj = x @ W_ih^T + (b_ih + b_hh)   -- [1M, 64] x [64, 128]
// 256-thread CTA, 64-sample tile, thread tile 4s x 8g.
// __launch_bounds__(256,2) caps regs at 128 -> 2 CTAs/SM (16 warps/SM).
// ============================================================================
#define XS   64     // samples per CTA
#define WPIT 34     // ull pitch (32 data + 2 pad)

__global__ void __launch_bounds__(256, 2)
xproj_kernel(const float* __restrict__ x,
             const float* __restrict__ W_ih,
             const float* __restrict__ b_ih,
             const float* __restrict__ b_hh)
{
    __shared__ __align__(16) ull wrow[NGATE * WPIT];  // 34816 B
    __shared__ __align__(16) ull xrow[XS * WPIT];     // 17408 B

    const int t  = threadIdx.x;
    const int tx = t & 15;               // gates: tx + 16p, p=0..7
    const int ty = t >> 4;               // samples: ty*4 .. ty*4+3
    const size_t row0 = (size_t)blockIdx.x * XS;

    // ---- stage W (32 KB) coalesced: 8 float4/thread ----
    {
        const float4* wg = reinterpret_cast<const float4*>(W_ih);
#pragma unroll
        for (int i = 0; i < 8; i++) {
            const int idx = t + 256 * i;      // float4 index, g-major
            const int g = idx >> 4;
            const int c = idx & 15;
            const float4 v = wg[idx];
            *reinterpret_cast<ulonglong2*>(&wrow[g * WPIT + 2 * c]) =
                make_ulonglong2(pack2(v.x, v.y), pack2(v.z, v.w));
        }
    }
    // ---- stage x tile (16 KB) coalesced: 4 float4/thread ----
    {
        const float4* xg = reinterpret_cast<const float4*>(x + row0 * F_IN);
#pragma unroll
        for (int i = 0; i < 4; i++) {
            const int idx = t + 256 * i;
            const int s = idx >> 4;
            const int c = idx & 15;
            const float4 v = xg[idx];
            *reinterpret_cast<ulonglong2*>(&xrow[s * WPIT + 2 * c]) =
                make_ulonglong2(pack2(v.x, v.y), pack2(v.z, v.w));
        }
    }

    // ---- acc init with bias in lo lane ----
    ull acc[4][8];
    {
#pragma unroll
        for (int p = 0; p < 8; p++) {
            const int g = tx + 16 * p;
            const ull b = pack2(b_ih[g] + b_hh[g], 0.0f);
#pragma unroll
            for (int q = 0; q < 4; q++) acc[q][p] = b;
        }
    }
    __syncthreads();

    // ---- main loop: per 2 kk: 12 LDS.128 feed 64 FFMA2 ----
#pragma unroll 4
    for (int kk = 0; kk < 32; kk += 2) {
        ulonglong2 xq[4], wq[8];
#pragma unroll
        for (int q = 0; q < 4; q++)
            xq[q] = *reinterpret_cast<const ulonglong2*>(
                &xrow[(ty * 4 + q) * WPIT + kk]);
#pragma unroll
        for (int p = 0; p < 8; p++)
            wq[p] = *reinterpret_cast<const ulonglong2*>(
                &wrow[(tx + 16 * p) * WPIT + kk]);
#pragma unroll
        for (int q = 0; q < 4; q++)
#pragma unroll
            for (int p = 0; p < 8; p++) {
                acc[q][p] = fma2(xq[q].x, wq[p].x, acc[q][p]);
                acc[q][p] = fma2(xq[q].y, wq[p].y, acc[q][p]);
            }
    }

    // ---- writeout: cell-major gate quads, coalesced STG.128 ----
#pragma unroll
    for (int q = 0; q < 4; q++) {
        float hlo, hhi;
        float4 v0, v1;
        unpack2(acc[q][0], hlo, hhi); v0.x = hlo + hhi;   // type 0, cell tx
        unpack2(acc[q][2], hlo, hhi); v0.y = hlo + hhi;   // type 1
        unpack2(acc[q][4], hlo, hhi); v0.z = hlo + hhi;   // type 2
        unpack2(acc[q][6], hlo, hhi); v0.w = hlo + hhi;   // type 3
        unpack2(acc[q][1], hlo, hhi); v1.x = hlo + hhi;   // cell tx+16
        unpack2(acc[q][3], hlo, hhi); v1.y = hlo + hhi;
        unpack2(acc[q][5], hlo, hhi); v1.z = hlo + hhi;
        unpack2(acc[q][7], hlo, hhi); v1.w = hlo + hhi;
        float4* op4 = reinterpret_cast<float4*>(
            g_xproj + (row0 + ty * 4 + q) * NGATE);
        op4[tx]      = v0;
        op4[tx + 16] = v1;
    }
}

// ============================================================================
// Kernel B: recurrence, single-warp CTA, TWO samples per warp.
// x_proj streamed via cp.async.cg into a 4-slot smem ring (group-tracked:
// the compiler cannot sink it; true 3-step prefetch shadow). Lane t owns
// cell t; copies and reads only its own 16B quad per sample.
// ============================================================================
__global__ void __launch_bounds__(32)
recur_kernel(const float* __restrict__ W_hh,
             const float* __restrict__ W_d,
             const float* __restrict__ b_d,
             float* __restrict__ out)
{
    __shared__ __align__(16) float4 xring[4][2][32];   // [slot][sample][lane] 4 KB
    __shared__ ull hp[2][2][HID / 2];                  // [buf][sample][kpair] 512 B

    const int t  = threadIdx.x;         // lane = cell index
    const int bA = blockIdx.x * 2;      // samples bA, bA+1

    // weight rows t, t+32, t+64, t+96 packed along k (shared by both samples)
    ull wI[16], wF[16], wG[16], wO[16];
    {
        const ull* wr = reinterpret_cast<const ull*>(W_hh);
#pragma unroll
        for (int kk = 0; kk < 16; kk++) {
            wI[kk] = wr[(t)      * 16 + kk];
            wF[kk] = wr[(t + 32) * 16 + kk];
            wG[kk] = wr[(t + 64) * 16 + kk];
            wO[kk] = wr[(t + 96) * 16 + kk];
        }
    }

    if (t < HID / 2) { hp[0][0][t] = 0ULL; hp[0][1][t] = 0ULL; }
    float cA = 0.0f, cB = 0.0f;

    const float4* gxA = reinterpret_cast<const float4*>(
        g_xproj + (size_t)bA * NGATE) + t;
    const float4* gxB = gxA + NGATE / 4;
    const size_t s4 = (size_t)BATCH * NGATE / 4;   // float4 step stride

    // prologue: slots 0..2 <- steps 0..2, one group per step
#pragma unroll
    for (int i = 0; i < PFD; i++) {
        cp16(&xring[i][0][t], gxA + (size_t)i * s4);
        cp16(&xring[i][1][t], gxB + (size_t)i * s4);
        asm volatile("cp.async.commit_group;");
    }
    __syncwarp();

#pragma unroll 1
    for (int ts0 = 0; ts0 < T_STEPS; ts0 += 4) {
#pragma unroll
        for (int u = 0; u < 4; u++) {
            const int ts = ts0 + u;
            // issue copy for step ts+PFD into the slot freed at step ts-1
            const int slot = (ts + PFD) & 3;
            cp16(&xring[slot][0][t], gxA + (size_t)(ts + PFD) * s4);
            cp16(&xring[slot][1][t], gxB + (size_t)(ts + PFD) * s4);
            asm volatile("cp.async.commit_group;");
            // step-ts group complete when <=3 groups pending
            asm volatile("cp.async.wait_group 3;");

            const float4 curA = xring[ts & 3][0][t];
            const float4 curB = xring[ts & 3][1][t];
            const int rb = ts & 1;
            const ulonglong2* hqA = reinterpret_cast<const ulonglong2*>(hp[rb][0]);
            const ulonglong2* hqB = reinterpret_cast<const ulonglong2*>(hp[rb][1]);

            // phase 1: 4 gate rows x 2 samples, h broadcast from smem
            ull aIA = pack2(curA.x, 0.0f), aFA = pack2(curA.y, 0.0f);
            ull aGA = pack2(curA.z, 0.0f), aOA = pack2(curA.w, 0.0f);
            ull aIB = pack2(curB.x, 0.0f), aFB = pack2(curB.y, 0.0f);
            ull aGB = pack2(curB.z, 0.0f), aOB = pack2(curB.w, 0.0f);
#pragma unroll
            for (int k2 = 0; k2 < 8; k2++) {
                const ulonglong2 hvA = hqA[k2];
                const ulonglong2 hvB = hqB[k2];
                aIA = fma2(hvA.x, wI[2 * k2], aIA);
                aIB = fma2(hvB.x, wI[2 * k2], aIB);
                aFA = fma2(hvA.x, wF[2 * k2], aFA);
                aFB = fma2(hvB.x, wF[2 * k2], aFB);
                aGA = fma2(hvA.x, wG[2 * k2], aGA);
                aGB = fma2(hvB.x, wG[2 * k2], aGB);
                aOA = fma2(hvA.x, wO[2 * k2], aOA);
                aOB = fma2(hvB.x, wO[2 * k2], aOB);
                aIA = fma2(hvA.y, wI[2 * k2 + 1], aIA);
                aIB = fma2(hvB.y, wI[2 * k2 + 1], aIB);
                aFA = fma2(hvA.y, wF[2 * k2 + 1], aFA);
                aFB = fma2(hvB.y, wF[2 * k2 + 1], aFB);
                aGA = fma2(hvA.y, wG[2 * k2 + 1], aGA);
                aGB = fma2(hvB.y, wG[2 * k2 + 1], aGB);
                aOA = fma2(hvA.y, wO[2 * k2 + 1], aOA);
                aOB = fma2(hvB.y, wO[2 * k2 + 1], aOB);
            }
            float lo, hi;
            unpack2(aIA, lo, hi); const float igA = sigm_fast(lo + hi);
            unpack2(aIB, lo, hi); const float igB = sigm_fast(lo + hi);
            unpack2(aFA, lo, hi); const float fgA = sigm_fast(lo + hi);
            unpack2(aFB, lo, hi); const float fgB = sigm_fast(lo + hi);
            unpack2(aGA, lo, hi); const float ggA = tanh_fast(lo + hi);
            unpack2(aGB, lo, hi); const float ggB = tanh_fast(lo + hi);
            unpack2(aOA, lo, hi); const float ogA = sigm_fast(lo + hi);
            unpack2(aOB, lo, hi); const float ogB = sigm_fast(lo + hi);

            // phase 2: thread-local cell updates, write to OTHER buffer
            cA = fgA * cA + igA * ggA;
            cB = fgB * cB + igB * ggB;
            const float hA = ogA * tanh_fast(cA);
            const float hB = ogB * tanh_fast(cB);
            reinterpret_cast<float*>(hp[1 - rb][0])[t] = hA;
            reinterpret_cast<float*>(hp[1 - rb][1])[t] = hB;

            __syncwarp();   // h buffer (1-rb) visible for next step
        }
    }

    // epilogue: out[b, a] = relu(h_T) @ W_d^T + b_d
    // final h in buffer 1-((T-1)&1) = T&1 = 0
    if ((t & 3) < 3 && t < 8) {
        const int s = t >> 2;       // 0 = sample A, 1 = sample B
        const int a = t & 3;        // action
        float sum = b_d[a];
        const float* hf = reinterpret_cast<const float*>(hp[T_STEPS & 1][s]);
#pragma unroll
        for (int j = 0; j < HID; j++)
            sum += fmaxf(hf[j], 0.0f) * W_d[a * HID + j];
        out[(size_t)(bA + s) * 3 + a] = sum;
    }
}

extern "C" void kernel_launch(void* const* d_in, const int* in_sizes, int n_in,
                              void* d_out, int out_size)
{
    const float* x    = (const float*)d_in[0];
    const float* W_ih = (const float*)d_in[1];
    const float* W_hh = (const float*)d_in[2];
    const float* b_ih = (const float*)d_in[3];
    const float* b_hh = (const float*)d_in[4];
    const float* W_d  = (const float*)d_in[5];
    const float* b_d  = (const float*)d_in[6];
    float* out = (float*)d_out;

    // Kernel A: x_proj GEMM over all timesteps (no recurrence)
    {
        dim3 grid((T_STEPS * BATCH) / XS);   // 16384 CTAs
        dim3 block(256);
        xproj_kernel<<<grid, block>>>(x, W_ih, b_ih, b_hh);
    }
    // Kernel B: sequential LSTM recurrence + decode head
    {
        dim3 grid(BATCH / 2);                // 1024 single-warp CTAs
        dim3 block(32);
        recur_kernel<<<grid, block>>>(W_hh, W_d, b_d, out);
    }
}